// round 1
// baseline (speedup 1.0000x reference)
#include <cuda_runtime.h>

#define F_NODES 16384
#define DEG 8
#define E (F_NODES * DEG)   // 131072
#define B 64
#define H 16
#define LAYERS 10

#define NPB 8               // nodes per block
#define TPN 16              // threads per node (4 batch elements each)
#define NODE_SMEM 280       // floats per node in smem (128 W1 + 128 W2 + 16 b1 + 8 b2)

typedef unsigned long long u64;

// Scratch: x transposed to (E, B). Three buffers: x0T (residual, layer-1 input)
// + ping/pong. Static __device__ arrays per allocation rules.
__device__ float g_x0T[(size_t)E * B];
__device__ float g_xA [(size_t)E * B];
__device__ float g_xB [(size_t)E * B];

__device__ __forceinline__ u64 pack2(float lo, float hi) {
    u64 r; asm("mov.b64 %0, {%1, %2};" : "=l"(r) : "f"(lo), "f"(hi)); return r;
}
__device__ __forceinline__ void unpack2(u64 v, float& lo, float& hi) {
    asm("mov.b64 {%0, %1}, %2;" : "=f"(lo), "=f"(hi) : "l"(v));
}
__device__ __forceinline__ void fma2(u64& d, u64 a, u64 b, u64 c) {
    asm("fma.rn.f32x2 %0, %1, %2, %3;" : "=l"(d) : "l"(a), "l"(b), "l"(c));
}
// Branchless ELU (alpha=1): max(x,0) + (exp(min(x,0)) - 1)
__device__ __forceinline__ float elu1(float x) {
    return fmaxf(x, 0.0f) + (__expf(fminf(x, 0.0f)) - 1.0f);
}

// (B, E) row-major -> (E, B)
__global__ void k_transpose_in(const float* __restrict__ in, float* __restrict__ out) {
    __shared__ float t[32][33];
    int e0 = blockIdx.x * 32, b0 = blockIdx.y * 32;
    int tx = threadIdx.x, ty = threadIdx.y;
    t[ty][tx] = in[(size_t)(b0 + ty) * E + e0 + tx];
    __syncthreads();
    out[(size_t)(e0 + ty) * B + b0 + tx] = t[tx][ty];
}

// (E, B) -> (B, E) row-major
__global__ void k_transpose_out(const float* __restrict__ in, float* __restrict__ out) {
    __shared__ float t[32][33];
    int e0 = blockIdx.x * 32, b0 = blockIdx.y * 32;
    int tx = threadIdx.x, ty = threadIdx.y;
    t[ty][tx] = in[(size_t)(e0 + ty) * B + b0 + tx];
    __syncthreads();
    out[(size_t)(b0 + ty) * E + e0 + tx] = t[tx][ty];
}

// One GSNN layer, all tensors in (E, B) transposed space.
// dst[(f*8+d)*B + b] = elu(g @ W1[f] + b1[f]) @ W2[f] + b2[f] + x0T[(f*8+d)*B + b]
__global__ __launch_bounds__(NPB * TPN)
void layer_kernel(const float* __restrict__ src, float* __restrict__ dst,
                  const float* __restrict__ W1, const float* __restrict__ b1,
                  const float* __restrict__ W2, const float* __restrict__ b2,
                  const int* __restrict__ in_ixs, const float* __restrict__ x0T) {
    __shared__ float sw[NPB * NODE_SMEM];
    const int tid  = threadIdx.x;
    const int nl   = tid >> 4;        // node within block
    const int q    = tid & 15;        // batch quad index (handles b = 4q..4q+3)
    const int node = blockIdx.x * NPB + nl;

    // Cooperative per-node weight staging (16 threads per node).
    {
        const float4* gW1 = (const float4*)(W1 + (size_t)node * 128);
        const float4* gW2 = (const float4*)(W2 + (size_t)node * 128);
        float4* s1 = (float4*)(sw + nl * NODE_SMEM);
        float4* s2 = (float4*)(sw + nl * NODE_SMEM + 128);
        s1[q * 2]     = gW1[q * 2];
        s1[q * 2 + 1] = gW1[q * 2 + 1];
        s2[q * 2]     = gW2[q * 2];
        s2[q * 2 + 1] = gW2[q * 2 + 1];
        sw[nl * NODE_SMEM + 256 + q] = b1[(size_t)node * 16 + q];
        if (q < 8) sw[nl * NODE_SMEM + 272 + q] = b2[(size_t)node * 8 + q];
    }
    __syncthreads();

    const float* w = sw + nl * NODE_SMEM;

    const int4 c0 = *(const int4*)(in_ixs + (size_t)node * 8);
    const int4 c1 = *(const int4*)(in_ixs + (size_t)node * 8 + 4);
    int cols[8] = {c0.x, c0.y, c0.z, c0.w, c1.x, c1.y, c1.z, c1.w};

    // Gather: 8 contiguous 256B columns; each thread takes its 16B slice.
    u64 g0[8], g1[8];
#pragma unroll
    for (int d = 0; d < 8; d++) {
        const float4 v = *(const float4*)(src + (((size_t)cols[d]) << 6) + (q << 2));
        g0[d] = pack2(v.x, v.y);
        g1[d] = pack2(v.z, v.w);
    }

    // Output accumulators (8 out dims x 4 batches), init with b2.
    u64 o0[8], o1[8];
#pragma unroll
    for (int d = 0; d < 8; d++) {
        float bd = w[272 + d];
        o0[d] = pack2(bd, bd);
        o1[d] = o0[d];
    }

    // Fused: for each hidden j, compute h_j then scatter into all 8 outputs.
#pragma unroll
    for (int j = 0; j < 16; j++) {
        float bj = w[256 + j];
        u64 a0 = pack2(bj, bj);
        u64 a1 = a0;
#pragma unroll
        for (int d = 0; d < 8; d++) {
            float wv = w[j * 8 + d];
            u64 wp = pack2(wv, wv);
            fma2(a0, g0[d], wp, a0);
            fma2(a1, g1[d], wp, a1);
        }
        float h0, h1, h2, h3;
        unpack2(a0, h0, h1);
        unpack2(a1, h2, h3);
        h0 = elu1(h0); h1 = elu1(h1); h2 = elu1(h2); h3 = elu1(h3);
        const u64 hh0 = pack2(h0, h1);
        const u64 hh1 = pack2(h2, h3);
#pragma unroll
        for (int d = 0; d < 8; d++) {
            float wv = w[128 + d * 16 + j];
            u64 wp = pack2(wv, wv);
            fma2(o0[d], hh0, wp, o0[d]);
            fma2(o1[d], hh1, wp, o1[d]);
        }
    }

    // Residual from x0T + store; output columns [8*node, 8*node+8) are contiguous.
#pragma unroll
    for (int d = 0; d < 8; d++) {
        const size_t col = (size_t)node * 8 + d;
        const float4 r = *(const float4*)(x0T + (col << 6) + (q << 2));
        float a, bb, c, dd;
        unpack2(o0[d], a, bb);
        unpack2(o1[d], c, dd);
        float4 outv = make_float4(a + r.x, bb + r.y, c + r.z, dd + r.w);
        *(float4*)(dst + (col << 6) + (q << 2)) = outv;
    }
}

extern "C" void kernel_launch(void* const* d_in, const int* in_sizes, int n_in,
                              void* d_out, int out_size) {
    const float* x0     = (const float*)d_in[0];
    const float* W1     = (const float*)d_in[1];
    const float* b1     = (const float*)d_in[2];
    const float* W2     = (const float*)d_in[3];
    const float* b2     = (const float*)d_in[4];
    const int*   in_ixs = (const int*)d_in[5];
    float* out = (float*)d_out;

    float *x0T, *xA, *xB;
    cudaGetSymbolAddress((void**)&x0T, g_x0T);
    cudaGetSymbolAddress((void**)&xA,  g_xA);
    cudaGetSymbolAddress((void**)&xB,  g_xB);

    dim3 tb(32, 32);
    k_transpose_in<<<dim3(E / 32, B / 32), tb>>>(x0, x0T);

    const float* src = x0T;
    float* bufs[2] = {xA, xB};
    for (int L = 0; L < LAYERS; L++) {
        float* dst = bufs[L & 1];
        layer_kernel<<<F_NODES / NPB, NPB * TPN>>>(src, dst, W1, b1, W2, b2, in_ixs, x0T);
        src = dst;
    }
    k_transpose_out<<<dim3(E / 32, B / 32), tb>>>(src, out);
}